// round 5
// baseline (speedup 1.0000x reference)
#include <cuda_runtime.h>
#include <cuda_fp16.h>
#include <math.h>

#define NCTA    128
#define NTH     512
#define HDIM    2048
#define G3      6144      // 3*H
#define IDIM    512
#define ODIM    512
#define JPC     16        // h elements per CTA
#define ROWS_PC 48        // 3 gates * JPC
#define MAXL    4096

// ---- scratch (static device allocations are allowed) ----
__device__ __align__(256) float  g_A[(size_t)MAXL * G3];       // precomputed gi (+biases)
__device__ __align__(256) __half g_w16[(size_t)G3 * HDIM];     // enc_w_hh fp16, CTA-major layout
__device__ __align__(256) float  g_h[2][HDIM];                 // double-buffered hidden state
__device__ __align__(256) float  g_logits[ODIM];
__device__ int g_count;

__device__ __forceinline__ float warp_sum(float v) {
#pragma unroll
    for (int off = 16; off; off >>= 1) v += __shfl_xor_sync(0xffffffffu, v, off);
    return v;
}

__device__ __forceinline__ void grid_sync(int target) {
    __threadfence();
    __syncthreads();
    if (threadIdx.x == 0) {
        atomicAdd(&g_count, 1);
        while (*((volatile int*)&g_count) < target) { }
    }
    __syncthreads();
}

// ---------------------------------------------------------------------------
__global__ void k_init() {
    int i = blockIdx.x * blockDim.x + threadIdx.x;
    if (i < HDIM) { g_h[0][i] = 0.f; g_h[1][i] = 0.f; }
    if (i == 0) g_count = 0;
}

// enc_w_hh (fp32, row-major [6144][2048]) -> fp16, laid out per-CTA:
// dst[(c*48 + (g*16+w)) * 2048 + k] = whh[(g*2048 + c*16 + w) * 2048 + k]
__global__ void k_convert(const float* __restrict__ whh) {
    size_t idx = (size_t)blockIdx.x * blockDim.x + threadIdx.x;
    if (idx >= (size_t)G3 * HDIM) return;
    int k   = (int)(idx & (HDIM - 1));
    int lrc = (int)(idx >> 11);
    int c   = lrc / ROWS_PC;
    int lr  = lrc - c * ROWS_PC;
    int g   = lr >> 4;
    int w   = lr & 15;
    int row = g * HDIM + c * JPC + w;
    g_w16[idx] = __float2half(whh[(size_t)row * HDIM + k]);
}

// A[t, n] = sum_k X[t,k] * Wih[n,k] + b_ih[n] + (n < 2H ? b_hh[n] : 0)
__global__ void k_gemm(const float* __restrict__ X, const float* __restrict__ W,
                       const float* __restrict__ bih, const float* __restrict__ bhh,
                       int L) {
    __shared__ float As[16][65];
    __shared__ float Bs[16][65];
    int n0 = blockIdx.x * 64, t0 = blockIdx.y * 64;
    int tid = threadIdx.x;
    int tx = tid & 15, ty = tid >> 4;
    float acc[4][4];
#pragma unroll
    for (int i = 0; i < 4; i++)
#pragma unroll
        for (int jj = 0; jj < 4; jj++) acc[i][jj] = 0.f;

    for (int k0 = 0; k0 < IDIM; k0 += 16) {
#pragma unroll
        for (int i = 0; i < 4; i++) {
            int idx = tid + i * 256;
            int r = idx >> 4, cc = idx & 15;
            int t = t0 + r;
            As[cc][r] = (t < L) ? X[(size_t)t * IDIM + k0 + cc] : 0.f;
            Bs[cc][r] = W[(size_t)(n0 + r) * IDIM + k0 + cc];
        }
        __syncthreads();
#pragma unroll
        for (int kk = 0; kk < 16; kk++) {
            float a[4], b[4];
#pragma unroll
            for (int i = 0; i < 4; i++) a[i] = As[kk][ty * 4 + i];
#pragma unroll
            for (int jj = 0; jj < 4; jj++) b[jj] = Bs[kk][tx * 4 + jj];
#pragma unroll
            for (int i = 0; i < 4; i++)
#pragma unroll
                for (int jj = 0; jj < 4; jj++) acc[i][jj] = fmaf(a[i], b[jj], acc[i][jj]);
        }
        __syncthreads();
    }
#pragma unroll
    for (int i = 0; i < 4; i++) {
        int t = t0 + ty * 4 + i;
        if (t >= L) continue;
#pragma unroll
        for (int jj = 0; jj < 4; jj++) {
            int n = n0 + tx * 4 + jj;
            float v = acc[i][jj] + bih[n] + ((n < 2 * HDIM) ? bhh[n] : 0.f);
            g_A[(size_t)t * G3 + n] = v;
        }
    }
}

// ---------------------------------------------------------------------------
// Persistent RNN kernel: 128 CTAs (1/SM), 512 threads. Warp w of CTA c owns
// h element j = c*16 + w and its three gate rows (r, z, n).
__global__ void __launch_bounds__(NTH, 1)
k_rnn(const float* __restrict__ enc_bhh,
      const float* __restrict__ dwih, const float* __restrict__ dwhh,
      const float* __restrict__ dbih, const float* __restrict__ dbhh,
      const float* __restrict__ how,  const float* __restrict__ hob,
      float* __restrict__ out, int L, int T) {
    extern __shared__ __half smw[];       // [48][2048] fp16 weights
    __shared__ float s_max, s_lse;
    __shared__ int   s_idx;

    const int c    = blockIdx.x;
    const int tid  = threadIdx.x;
    const int w    = tid >> 5;
    const int lane = tid & 31;
    const int j    = c * JPC + w;

    // load this CTA's encoder weight slice into shared memory
    {
        const uint4* src = reinterpret_cast<const uint4*>(g_w16 + (size_t)c * ROWS_PC * HDIM);
        uint4* dst = reinterpret_cast<uint4*>(smw);
        for (int i = tid; i < ROWS_PC * HDIM / 8; i += NTH) dst[i] = src[i];
    }

    float hreg[64];                       // h[k] for k = c8*256 + lane*8 + q
#pragma unroll
    for (int i = 0; i < 64; i++) hreg[i] = 0.f;
    float hold = 0.f;                     // lane0: current h[j]
    float bhn  = enc_bhh[2 * HDIM + j];   // used by lane0 only
    int epoch = 0;
    __syncthreads();

    // ---------------- encoder: L sequential GRU steps ----------------
    for (int t = 0; t < L; t++) {
        float Ar = 0.f, Az = 0.f, An = 0.f;
        if (lane == 0) {
            const float* Ab = g_A + (size_t)t * G3 + j;
            Ar = __ldg(Ab);
            Az = __ldg(Ab + HDIM);
            An = __ldg(Ab + 2 * HDIM);
        }
        float dots[3];
#pragma unroll
        for (int g = 0; g < 3; g++) {
            const __half* wrow = smw + (size_t)(g * JPC + w) * HDIM;
            float a0 = 0.f, a1 = 0.f, a2 = 0.f, a3 = 0.f;
#pragma unroll
            for (int c8 = 0; c8 < 8; c8++) {
                uint4 p = *reinterpret_cast<const uint4*>(wrow + c8 * 256 + lane * 8);
                float2 f0 = __half22float2(*reinterpret_cast<__half2*>(&p.x));
                float2 f1 = __half22float2(*reinterpret_cast<__half2*>(&p.y));
                float2 f2 = __half22float2(*reinterpret_cast<__half2*>(&p.z));
                float2 f3 = __half22float2(*reinterpret_cast<__half2*>(&p.w));
                a0 = fmaf(f0.x, hreg[c8 * 8 + 0], a0);
                a1 = fmaf(f0.y, hreg[c8 * 8 + 1], a1);
                a2 = fmaf(f1.x, hreg[c8 * 8 + 2], a2);
                a3 = fmaf(f1.y, hreg[c8 * 8 + 3], a3);
                a0 = fmaf(f2.x, hreg[c8 * 8 + 4], a0);
                a1 = fmaf(f2.y, hreg[c8 * 8 + 5], a1);
                a2 = fmaf(f3.x, hreg[c8 * 8 + 6], a2);
                a3 = fmaf(f3.y, hreg[c8 * 8 + 7], a3);
            }
            dots[g] = warp_sum((a0 + a1) + (a2 + a3));
        }
        if (lane == 0) {
            float r = 1.f / (1.f + expf(-(dots[0] + Ar)));
            float z = 1.f / (1.f + expf(-(dots[1] + Az)));
            float n = tanhf(An + r * (dots[2] + bhn));
            hold = (1.f - z) * n + z * hold;
            g_h[(t + 1) & 1][j] = hold;
        }
        epoch++;
        grid_sync(epoch * NCTA);
        // reload h into registers (L2-only loads: L1 is stale across CTAs)
        const float* hb = g_h[(t + 1) & 1];
#pragma unroll
        for (int c8 = 0; c8 < 8; c8++) {
            const float4* p = reinterpret_cast<const float4*>(hb + c8 * 256 + lane * 8);
            float4 v0 = __ldcg(p);
            float4 v1 = __ldcg(p + 1);
            hreg[c8 * 8 + 0] = v0.x; hreg[c8 * 8 + 1] = v0.y;
            hreg[c8 * 8 + 2] = v0.z; hreg[c8 * 8 + 3] = v0.w;
            hreg[c8 * 8 + 4] = v1.x; hreg[c8 * 8 + 5] = v1.y;
            hreg[c8 * 8 + 6] = v1.z; hreg[c8 * 8 + 7] = v1.w;
        }
    }

    // ---------------- autoregressive decoder ----------------
    float bir = 0.f, biz = 0.f, bin = 0.f, bhnd = 0.f;
    if (lane == 0) {
        bir  = dbih[j] + dbhh[j];
        biz  = dbih[HDIM + j] + dbhh[HDIM + j];
        bin  = dbih[2 * HDIM + j];
        bhnd = dbhh[2 * HDIM + j];
    }
    int idx = -1;   // one-hot index; -1 means zero input (first step)

    for (int s = 0; s < T; s++) {
        int par = (L + s) & 1;            // h currently lives in g_h[par]
        // --- phase A: GRU step (fp32 weights from L2) ---
        float dots[3];
#pragma unroll
        for (int g = 0; g < 3; g++) {
            const float* wrow = dwhh + (size_t)(g * HDIM + j) * HDIM;
            float a0 = 0.f, a1 = 0.f, a2 = 0.f, a3 = 0.f;
#pragma unroll
            for (int c8 = 0; c8 < 8; c8++) {
                const float4* p = reinterpret_cast<const float4*>(wrow + c8 * 256 + lane * 8);
                float4 v0 = __ldg(p);
                float4 v1 = __ldg(p + 1);
                a0 = fmaf(v0.x, hreg[c8 * 8 + 0], a0);
                a1 = fmaf(v0.y, hreg[c8 * 8 + 1], a1);
                a2 = fmaf(v0.z, hreg[c8 * 8 + 2], a2);
                a3 = fmaf(v0.w, hreg[c8 * 8 + 3], a3);
                a0 = fmaf(v1.x, hreg[c8 * 8 + 4], a0);
                a1 = fmaf(v1.y, hreg[c8 * 8 + 5], a1);
                a2 = fmaf(v1.z, hreg[c8 * 8 + 6], a2);
                a3 = fmaf(v1.w, hreg[c8 * 8 + 7], a3);
            }
            dots[g] = warp_sum((a0 + a1) + (a2 + a3));
        }
        if (lane == 0) {
            float gr = bir, gz = biz, gn = bin;
            if (idx >= 0) {   // one-hot input -> column gather of dec_w_ih
                gr += __ldg(dwih + (size_t)j * ODIM + idx);
                gz += __ldg(dwih + (size_t)(HDIM + j) * ODIM + idx);
                gn += __ldg(dwih + (size_t)(2 * HDIM + j) * ODIM + idx);
            }
            float r = 1.f / (1.f + expf(-(dots[0] + gr)));
            float z = 1.f / (1.f + expf(-(dots[1] + gz)));
            float n = tanhf(gn + r * (dots[2] + bhnd));
            hold = (1.f - z) * n + z * hold;
            g_h[par ^ 1][j] = hold;
        }
        epoch++;
        grid_sync(epoch * NCTA);
        {
            const float* hb = g_h[par ^ 1];
#pragma unroll
            for (int c8 = 0; c8 < 8; c8++) {
                const float4* p = reinterpret_cast<const float4*>(hb + c8 * 256 + lane * 8);
                float4 v0 = __ldcg(p);
                float4 v1 = __ldcg(p + 1);
                hreg[c8 * 8 + 0] = v0.x; hreg[c8 * 8 + 1] = v0.y;
                hreg[c8 * 8 + 2] = v0.z; hreg[c8 * 8 + 3] = v0.w;
                hreg[c8 * 8 + 4] = v1.x; hreg[c8 * 8 + 5] = v1.y;
                hreg[c8 * 8 + 6] = v1.z; hreg[c8 * 8 + 7] = v1.w;
            }
        }
        // --- phase B: logits = h_new @ h2o_w^T + b (4 rows per CTA) ---
        float mylogit = 0.f;
        if (w < 4) {
            int row = c * 4 + w;
            const float* wrow = how + (size_t)row * HDIM;
            float a0 = 0.f, a1 = 0.f, a2 = 0.f, a3 = 0.f;
#pragma unroll
            for (int c8 = 0; c8 < 8; c8++) {
                const float4* p = reinterpret_cast<const float4*>(wrow + c8 * 256 + lane * 8);
                float4 v0 = __ldg(p);
                float4 v1 = __ldg(p + 1);
                a0 = fmaf(v0.x, hreg[c8 * 8 + 0], a0);
                a1 = fmaf(v0.y, hreg[c8 * 8 + 1], a1);
                a2 = fmaf(v0.z, hreg[c8 * 8 + 2], a2);
                a3 = fmaf(v0.w, hreg[c8 * 8 + 3], a3);
                a0 = fmaf(v1.x, hreg[c8 * 8 + 4], a0);
                a1 = fmaf(v1.y, hreg[c8 * 8 + 5], a1);
                a2 = fmaf(v1.z, hreg[c8 * 8 + 6], a2);
                a3 = fmaf(v1.w, hreg[c8 * 8 + 7], a3);
            }
            float acc = warp_sum((a0 + a1) + (a2 + a3));
            if (lane == 0) {
                mylogit = acc + __ldg(hob + row);
                g_logits[row] = mylogit;
            }
        }
        epoch++;
        grid_sync(epoch * NCTA);
        // --- phase C: softmax stats + argmax (redundant per CTA, deterministic) ---
        if (w == 0) {
            float v[16];
#pragma unroll
            for (int q = 0; q < 16; q++) v[q] = __ldcg(g_logits + q * 32 + lane);
            float mx = v[0]; int mi = lane;
#pragma unroll
            for (int q = 1; q < 16; q++)
                if (v[q] > mx) { mx = v[q]; mi = q * 32 + lane; }
#pragma unroll
            for (int off = 16; off; off >>= 1) {
                float om = __shfl_xor_sync(0xffffffffu, mx, off);
                int   oi = __shfl_xor_sync(0xffffffffu, mi, off);
                if (om > mx || (om == mx && oi < mi)) { mx = om; mi = oi; }
            }
            float se = 0.f;
#pragma unroll
            for (int q = 0; q < 16; q++) se += expf(v[q] - mx);
            se = warp_sum(se);
            if (lane == 0) { s_max = mx; s_lse = logf(se); s_idx = mi; }
        }
        __syncthreads();
        idx = s_idx;
        if (w < 4 && lane == 0)
            out[(size_t)s * ODIM + c * 4 + w] = mylogit - s_max - s_lse;
        epoch++;
        grid_sync(epoch * NCTA);   // protect g_logits reuse next step
    }
}

// ---------------------------------------------------------------------------
extern "C" void kernel_launch(void* const* d_in, const int* in_sizes, int n_in,
                              void* d_out, int out_size) {
    const float* input_   = (const float*)d_in[0];
    const float* enc_w_ih = (const float*)d_in[1];
    const float* enc_w_hh = (const float*)d_in[2];
    const float* enc_b_ih = (const float*)d_in[3];
    const float* enc_b_hh = (const float*)d_in[4];
    const float* dec_w_ih = (const float*)d_in[5];
    const float* dec_w_hh = (const float*)d_in[6];
    const float* dec_b_ih = (const float*)d_in[7];
    const float* dec_b_hh = (const float*)d_in[8];
    const float* h2o_w    = (const float*)d_in[9];
    const float* h2o_b    = (const float*)d_in[10];

    int L = in_sizes[0] / IDIM;
    if (L > MAXL) L = MAXL;
    int T = out_size / ODIM;

    // opt-in large dynamic shared memory (idempotent, not a stream op)
    cudaFuncSetAttribute(k_rnn, cudaFuncAttributeMaxDynamicSharedMemorySize,
                         ROWS_PC * HDIM * (int)sizeof(__half));

    k_init<<<8, 256>>>();
    {
        size_t total = (size_t)G3 * HDIM;
        int grid = (int)((total + 255) / 256);
        k_convert<<<grid, 256>>>(enc_w_hh);
    }
    {
        dim3 gg(G3 / 64, (L + 63) / 64);
        k_gemm<<<gg, 256>>>(input_, enc_w_ih, enc_b_ih, enc_b_hh, L);
    }
    k_rnn<<<NCTA, NTH, ROWS_PC * HDIM * (int)sizeof(__half)>>>(
        enc_b_hh, dec_w_ih, dec_w_hh, dec_b_ih, dec_b_hh,
        h2o_w, h2o_b, (float*)d_out, L, T);
}